// round 12
// baseline (speedup 1.0000x reference)
#include <cuda_runtime.h>
#include <cuda_fp16.h>
#include <cstdint>

#define PAIRS   16384
#define NBLOCKS 4096         // 16384 pairs / 4 per block-iteration
#define NT      512          // 16 warps, 1 CTA/SM (persistent)
#define GRID    152          // GB300 SM count

// ---------------- smem layout (bytes) ----------------
#define SM_A_HI  0u          // 64x128 fp16 swizzled (zn, later o_hi)
#define SM_A_LO  16384u      // zn_lo / o_lo
#define W_OFF(m) (32768u + (uint32_t)(m) * 32768u)   // 5 resident W images
#define SM_Z     196608u     // 64x128 fp32 raw z prefetch buffer (32KB)
#define SMEM_TOTAL 229376u

// ---------------- W images: 5 mats x 128x128 fp16, [n][k] ----------------
__device__ __half g_wimg[5 * 16384];

// ---------------- helpers ----------------
__device__ __forceinline__ uint32_t smem_u32(const void* p) {
    uint32_t a;
    asm("{ .reg .u64 t; cvta.to.shared.u64 t, %1; cvt.u32.u64 %0, t; }" : "=r"(a) : "l"(p));
    return a;
}
__device__ __forceinline__ float sigmoidf_(float x) { return 1.0f / (1.0f + __expf(-x)); }

__device__ __forceinline__ void ldmX4(uint32_t r[4], uint32_t addr) {
    asm volatile("ldmatrix.sync.aligned.m8n8.x4.shared.b16 {%0,%1,%2,%3}, [%4];"
                 : "=r"(r[0]), "=r"(r[1]), "=r"(r[2]), "=r"(r[3]) : "r"(addr));
}
__device__ __forceinline__ void mma_f16(float c[4], const uint32_t a[4], const uint32_t b[2]) {
    asm volatile(
        "mma.sync.aligned.m16n8k16.row.col.f32.f16.f16.f32 "
        "{%0,%1,%2,%3}, {%4,%5,%6,%7}, {%8,%9}, {%0,%1,%2,%3};"
        : "+f"(c[0]), "+f"(c[1]), "+f"(c[2]), "+f"(c[3])
        : "r"(a[0]), "r"(a[1]), "r"(a[2]), "r"(a[3]), "r"(b[0]), "r"(b[1]));
}
__device__ __forceinline__ uint32_t movm(uint32_t a) {
    uint32_t d;
    asm volatile("movmatrix.sync.aligned.m8n8.trans.b16 %0, %1;" : "=r"(d) : "r"(a));
    return d;
}
__device__ __forceinline__ void cp_async16(uint32_t dst, const void* src) {
    asm volatile("cp.async.ca.shared.global [%0], [%1], 16;" :: "r"(dst), "l"(src));
}
__device__ __forceinline__ void cp_commit() { asm volatile("cp.async.commit_group;"); }
#define CP_WAIT(n) asm volatile("cp.async.wait_group %0;" :: "n"(n))

__device__ __forceinline__ uint32_t h2bits(float x, float y) {
    __half2 h = __floats2half2_rn(x, y);
    return *(uint32_t*)&h;
}
__device__ __forceinline__ uint32_t h2res(float x, float y, uint32_t hb) {
    __half2 h = *(__half2*)&hb;
    float2 f = __half22float2(h);
    __half2 l = __floats2half2_rn(x - f.x, y - f.y);
    return *(uint32_t*)&l;
}

// =====================================================================================
// prep: round W to fp16, transpose to [n][k]
// =====================================================================================
__global__ void kernel_prep(const float* __restrict__ Wq, const float* __restrict__ Wk,
                            const float* __restrict__ Wv, const float* __restrict__ Wg,
                            const float* __restrict__ Wo)
{
    const int m = blockIdx.x;
    const float* W = (m == 0) ? Wq : (m == 1) ? Wk : (m == 2) ? Wv : (m == 3) ? Wg : Wo;
    __half* hi = g_wimg + (long long)m * 16384;
    for (int idx = threadIdx.x; idx < 16384; idx += blockDim.x) {
        const int n = idx >> 7, k = idx & 127;
        hi[n * 128 + k] = __float2half_rn(W[k * 128 + n]);
    }
}

// ---------------- building blocks ----------------
__device__ __forceinline__ void stage_img(uint32_t base, uint32_t dstOff,
                                          const __half* img, int t)
{
    #pragma unroll
    for (int it = 0; it < 4; ++it) {
        const int idx = t + it * NT;
        const uint32_t row = (uint32_t)(idx >> 4), c = (uint32_t)(idx & 15);
        cp_async16(base + dstOff + row * 256u + ((c ^ (row & 7u)) << 4),
                   img + row * 128u + c * 8u);
    }
}

// prefetch raw z tile (64 rows x 128 fp32) for pair-block pbase into SM_Z
__device__ __forceinline__ void stage_z(uint32_t base, const float* __restrict__ z,
                                        int pbase, int t)
{
    #pragma unroll
    for (int it = 0; it < 4; ++it) {
        const int idx = t + it * NT;            // 2048 chunks of 16B
        const int row = idx >> 5, c = idx & 31;
        const long long grow = (long long)(row & 15) * PAIRS + pbase + (row >> 4);
        cp_async16(base + SM_Z + (uint32_t)row * 512u + (uint32_t)c * 16u,
                   z + grow * 128 + c * 4);
    }
}

// fused single+single: cq += Ah*B0, ck += Ah*B1 (shared A loads, x4 B loads)
__device__ __forceinline__ void gemm_qk(uint32_t base, uint32_t b0Off, uint32_t b1Off,
                                        int wm, int wn, int lane,
                                        float cq[4][4], float ck[4][4])
{
    const uint32_t arow = (uint32_t)(wm * 16 + (lane & 15));
    const uint32_t asel = (uint32_t)(lane >> 4);
    const uint32_t brow = (uint32_t)(wn * 32 + (lane & 7) + ((lane >> 4) << 3));
    const uint32_t bsel = (uint32_t)((lane >> 3) & 1);
    #pragma unroll
    for (int k = 0; k < 8; ++k) {
        uint32_t ah[4], b0[2][4], b1[2][4];
        const uint32_t c16 = (uint32_t)(k * 2) + asel;
        ldmX4(ah, base + SM_A_HI + arow * 256u + ((c16 ^ (arow & 7u)) << 4));
        const uint32_t bc = (uint32_t)(k * 2) + bsel;
        #pragma unroll
        for (int nbp = 0; nbp < 2; ++nbp) {
            const uint32_t row = brow + (uint32_t)nbp * 16u;
            const uint32_t off = row * 256u + ((bc ^ (row & 7u)) << 4);
            ldmX4(b0[nbp], base + b0Off + off);
            ldmX4(b1[nbp], base + b1Off + off);
        }
        #pragma unroll
        for (int nbp = 0; nbp < 2; ++nbp) {
            mma_f16(cq[nbp*2],   ah, &b0[nbp][0]);
            mma_f16(cq[nbp*2+1], ah, &b0[nbp][2]);
            mma_f16(ck[nbp*2],   ah, &b1[nbp][0]);
            mma_f16(ck[nbp*2+1], ah, &b1[nbp][2]);
        }
    }
}

// fused dual+single: cv += (Ah+Al)*B0, cg += Ah*B1
__device__ __forceinline__ void gemm_vg(uint32_t base, uint32_t b0Off, uint32_t b1Off,
                                        int wm, int wn, int lane,
                                        float cv[4][4], float cg[4][4])
{
    const uint32_t arow = (uint32_t)(wm * 16 + (lane & 15));
    const uint32_t asel = (uint32_t)(lane >> 4);
    const uint32_t brow = (uint32_t)(wn * 32 + (lane & 7) + ((lane >> 4) << 3));
    const uint32_t bsel = (uint32_t)((lane >> 3) & 1);
    #pragma unroll
    for (int k = 0; k < 8; ++k) {
        uint32_t ah[4], al[4], b0[2][4], b1[2][4];
        const uint32_t c16 = (uint32_t)(k * 2) + asel;
        const uint32_t ad = base + arow * 256u + ((c16 ^ (arow & 7u)) << 4);
        ldmX4(ah, ad + SM_A_HI);
        ldmX4(al, ad + SM_A_LO);
        const uint32_t bc = (uint32_t)(k * 2) + bsel;
        #pragma unroll
        for (int nbp = 0; nbp < 2; ++nbp) {
            const uint32_t row = brow + (uint32_t)nbp * 16u;
            const uint32_t off = row * 256u + ((bc ^ (row & 7u)) << 4);
            ldmX4(b0[nbp], base + b0Off + off);
            ldmX4(b1[nbp], base + b1Off + off);
        }
        #pragma unroll
        for (int nbp = 0; nbp < 2; ++nbp) {
            mma_f16(cv[nbp*2],   ah, &b0[nbp][0]);
            mma_f16(cv[nbp*2+1], ah, &b0[nbp][2]);
            mma_f16(cg[nbp*2],   ah, &b1[nbp][0]);
            mma_f16(cg[nbp*2+1], ah, &b1[nbp][2]);
            mma_f16(cv[nbp*2],   al, &b0[nbp][0]);
            mma_f16(cv[nbp*2+1], al, &b0[nbp][2]);
        }
    }
}

// dual pass for out GEMM: c += (Ah+Al)*B
__device__ __forceinline__ void gemm_dual(uint32_t base, uint32_t bOff, int wm, int wn,
                                          int lane, float c[4][4])
{
    const uint32_t arow = (uint32_t)(wm * 16 + (lane & 15));
    const uint32_t asel = (uint32_t)(lane >> 4);
    const uint32_t brow = (uint32_t)(wn * 32 + (lane & 7) + ((lane >> 4) << 3));
    const uint32_t bsel = (uint32_t)((lane >> 3) & 1);
    #pragma unroll
    for (int k = 0; k < 8; ++k) {
        uint32_t ah[4], al[4], b[2][4];
        const uint32_t c16 = (uint32_t)(k * 2) + asel;
        const uint32_t ad = base + arow * 256u + ((c16 ^ (arow & 7u)) << 4);
        ldmX4(ah, ad + SM_A_HI);
        ldmX4(al, ad + SM_A_LO);
        const uint32_t bc = (uint32_t)(k * 2) + bsel;
        #pragma unroll
        for (int nbp = 0; nbp < 2; ++nbp) {
            const uint32_t row = brow + (uint32_t)nbp * 16u;
            ldmX4(b[nbp], base + bOff + row * 256u + ((bc ^ (row & 7u)) << 4));
        }
        #pragma unroll
        for (int nbp = 0; nbp < 2; ++nbp) {
            mma_f16(c[nbp*2],   ah, &b[nbp][0]);
            mma_f16(c[nbp*2+1], ah, &b[nbp][2]);
            mma_f16(c[nbp*2],   al, &b[nbp][0]);
            mma_f16(c[nbp*2+1], al, &b[nbp][2]);
        }
    }
}

// LN: split 4 floats -> hi/lo fp16 into swizzled A tiles
__device__ __forceinline__ void store_a4(char* smem, int r, int lane, float4 v)
{
    const uint32_t chunk = (uint32_t)(lane >> 1);
    const uint32_t addr = (uint32_t)r * 256u + ((chunk ^ (uint32_t)(r & 7)) << 4)
                        + (uint32_t)((lane & 1) * 8);
    const __half hx = __float2half_rn(v.x), hy = __float2half_rn(v.y);
    const __half hz = __float2half_rn(v.z), hw = __float2half_rn(v.w);
    const __half2 h01 = __halves2half2(hx, hy), h23 = __halves2half2(hz, hw);
    const __half2 l01 = __halves2half2(__float2half_rn(v.x - __half2float(hx)),
                                       __float2half_rn(v.y - __half2float(hy)));
    const __half2 l23 = __halves2half2(__float2half_rn(v.z - __half2float(hz)),
                                       __float2half_rn(v.w - __half2float(hw)));
    *(__half2*)(smem + SM_A_HI + addr)     = h01;
    *(__half2*)(smem + SM_A_HI + addr + 4) = h23;
    *(__half2*)(smem + SM_A_LO + addr)     = l01;
    *(__half2*)(smem + SM_A_LO + addr + 4) = l23;
}

// hi/lo split store of one half2 into the A tiles
__device__ __forceinline__ void store_o2(char* smem, int row, int col, float x, float y)
{
    const uint32_t chunk = (uint32_t)(col >> 3);
    const uint32_t off = (uint32_t)row * 256u + ((chunk ^ (uint32_t)(row & 7)) << 4)
                       + (uint32_t)((col & 7) * 2);
    const __half2 h = __floats2half2_rn(x, y);
    const float2 f = __half22float2(h);
    const __half2 l = __floats2half2_rn(x - f.x, y - f.y);
    *(__half2*)(smem + SM_A_HI + off) = h;
    *(__half2*)(smem + SM_A_LO + off) = l;
}

__device__ __forceinline__ const __half* wimg(int mat) {
    return g_wimg + (long long)mat * 16384;
}

// =====================================================================================
// persistent fused kernel: 5 W images resident; z software-pipelined via cp.async
// 4 pairs per iteration, 16 warps; warp (wm=pair, wn=head-pair)
// =====================================================================================
__global__ __launch_bounds__(NT, 1)
void kernel_fused(const float* __restrict__ z,
                  const float* __restrict__ lnw, const float* __restrict__ lnb,
                  const float* __restrict__ bg,  const float* __restrict__ bo,
                  float* __restrict__ out)
{
    extern __shared__ char smem[];
    const uint32_t base = smem_u32(smem);

    const int t = threadIdx.x, lane = t & 31, warp = t >> 5;
    const int wm = warp >> 2, wn = warp & 3;

    // ---------- stage all 5 W images + first z tile ----------
    #pragma unroll
    for (int m = 0; m < 5; ++m)
        stage_img(base, W_OFF(m), wimg(m), t);
    stage_z(base, z, blockIdx.x * 4, t);
    cp_commit();

    const float4 lw = *(const float4*)&lnw[lane * 4];
    const float4 lb = *(const float4*)&lnb[lane * 4];

    for (int blk = blockIdx.x; blk < NBLOCKS; blk += gridDim.x) {
        const int pbase = blk * 4;
        CP_WAIT(0);                  // z tile (and W on iter 0) landed
        __syncthreads();             // also: prior iteration's A reads done

        // ---------- LayerNorm from smem z -> zn hi/lo ----------
        for (int r = warp; r < 64; r += 16) {
            const float4 zv = *(const float4*)(smem + SM_Z + (uint32_t)r * 512u
                                               + (uint32_t)lane * 16u);
            float s  = zv.x + zv.y + zv.z + zv.w;
            float s2 = zv.x*zv.x + zv.y*zv.y + zv.z*zv.z + zv.w*zv.w;
            #pragma unroll
            for (int off = 16; off > 0; off >>= 1) {
                s  += __shfl_xor_sync(0xffffffffu, s,  off);
                s2 += __shfl_xor_sync(0xffffffffu, s2, off);
            }
            const float mu   = s * (1.0f / 128.0f);
            const float var  = s2 * (1.0f / 128.0f) - mu * mu;
            const float rstd = rsqrtf(var + 1e-5f);
            float4 o;
            o.x = (zv.x - mu) * rstd * lw.x + lb.x;
            o.y = (zv.y - mu) * rstd * lw.y + lb.y;
            o.z = (zv.z - mu) * rstd * lw.z + lb.z;
            o.w = (zv.w - mu) * rstd * lw.w + lb.w;
            store_a4(smem, r, lane, o);
        }
        __syncthreads();             // zn ready; z buffer consumed

        // prefetch next iteration's z into the (now free) z buffer
        if (blk + (int)gridDim.x < NBLOCKS) {
            stage_z(base, z, (blk + gridDim.x) * 4, t);
            cp_commit();
        }

        // ---------- fused q|k -> S -> softmax -> P fragments ----------
        uint32_t pf[2][4], plf[2][4];
        {
            float cq[4][4], ck[4][4];
            #pragma unroll
            for (int j = 0; j < 4; ++j)
                #pragma unroll
                for (int q = 0; q < 4; ++q) { cq[j][q] = 0.f; ck[j][q] = 0.f; }
            gemm_qk(base, W_OFF(0), W_OFF(1), wm, wn, lane, cq, ck);

            #pragma unroll
            for (int hh = 0; hh < 2; ++hh) {
                uint32_t qf[4], kf[4];
                qf[0] = h2bits(cq[2*hh][0],   cq[2*hh][1]);
                qf[1] = h2bits(cq[2*hh][2],   cq[2*hh][3]);
                qf[2] = h2bits(cq[2*hh+1][0], cq[2*hh+1][1]);
                qf[3] = h2bits(cq[2*hh+1][2], cq[2*hh+1][3]);
                kf[0] = h2bits(ck[2*hh][0],   ck[2*hh][1]);
                kf[1] = h2bits(ck[2*hh+1][0], ck[2*hh+1][1]);
                kf[2] = h2bits(ck[2*hh][2],   ck[2*hh][3]);
                kf[3] = h2bits(ck[2*hh+1][2], ck[2*hh+1][3]);

                float s0[4] = {0.f,0.f,0.f,0.f}, s1[4] = {0.f,0.f,0.f,0.f};
                mma_f16(s0, qf, &kf[0]);
                mma_f16(s1, qf, &kf[2]);
                #pragma unroll
                for (int q = 0; q < 4; ++q) { s0[q] *= 0.25f; s1[q] *= 0.25f; }

                float mlo = fmaxf(fmaxf(s0[0], s0[1]), fmaxf(s1[0], s1[1]));
                float mhi = fmaxf(fmaxf(s0[2], s0[3]), fmaxf(s1[2], s1[3]));
                mlo = fmaxf(mlo, __shfl_xor_sync(0xffffffffu, mlo, 1));
                mlo = fmaxf(mlo, __shfl_xor_sync(0xffffffffu, mlo, 2));
                mhi = fmaxf(mhi, __shfl_xor_sync(0xffffffffu, mhi, 1));
                mhi = fmaxf(mhi, __shfl_xor_sync(0xffffffffu, mhi, 2));
                s0[0] = __expf(s0[0] - mlo); s0[1] = __expf(s0[1] - mlo);
                s1[0] = __expf(s1[0] - mlo); s1[1] = __expf(s1[1] - mlo);
                s0[2] = __expf(s0[2] - mhi); s0[3] = __expf(s0[3] - mhi);
                s1[2] = __expf(s1[2] - mhi); s1[3] = __expf(s1[3] - mhi);
                float slo = s0[0] + s0[1] + s1[0] + s1[1];
                float shi = s0[2] + s0[3] + s1[2] + s1[3];
                slo += __shfl_xor_sync(0xffffffffu, slo, 1);
                slo += __shfl_xor_sync(0xffffffffu, slo, 2);
                shi += __shfl_xor_sync(0xffffffffu, shi, 1);
                shi += __shfl_xor_sync(0xffffffffu, shi, 2);
                const float ilo = 1.0f / slo, ihi = 1.0f / shi;
                s0[0] *= ilo; s0[1] *= ilo; s1[0] *= ilo; s1[1] *= ilo;
                s0[2] *= ihi; s0[3] *= ihi; s1[2] *= ihi; s1[3] *= ihi;

                pf[hh][0] = h2bits(s0[0], s0[1]);  plf[hh][0] = h2res(s0[0], s0[1], pf[hh][0]);
                pf[hh][1] = h2bits(s0[2], s0[3]);  plf[hh][1] = h2res(s0[2], s0[3], pf[hh][1]);
                pf[hh][2] = h2bits(s1[0], s1[1]);  plf[hh][2] = h2res(s1[0], s1[1], pf[hh][2]);
                pf[hh][3] = h2bits(s1[2], s1[3]);  plf[hh][3] = h2res(s1[2], s1[3], pf[hh][3]);
            }
        }

        // ---------- fused v(dual)|g -> O = P V -> gate -> store o ----------
        float oc[2][2][4];
        {
            float cv[4][4], cg[4][4];
            #pragma unroll
            for (int j = 0; j < 4; ++j)
                #pragma unroll
                for (int q = 0; q < 4; ++q) { cv[j][q] = 0.f; cg[j][q] = 0.f; }
            gemm_vg(base, W_OFF(2), W_OFF(3), wm, wn, lane, cv, cg);

            #pragma unroll
            for (int hh = 0; hh < 2; ++hh) {
                #pragma unroll
                for (int cb = 0; cb < 2; ++cb) {
                    const int nb = hh * 2 + cb;
                    const uint32_t m0 = h2bits(cv[nb][0], cv[nb][1]);
                    const uint32_t m1 = h2bits(cv[nb][2], cv[nb][3]);
                    const uint32_t r0 = h2res(cv[nb][0], cv[nb][1], m0);
                    const uint32_t r1 = h2res(cv[nb][2], cv[nb][3], m1);
                    uint32_t bh[2], bl[2];
                    bh[0] = movm(m0); bh[1] = movm(m1);
                    bl[0] = movm(r0); bl[1] = movm(r1);
                    float* o = oc[hh][cb];
                    o[0] = 0.f; o[1] = 0.f; o[2] = 0.f; o[3] = 0.f;
                    mma_f16(o, pf[hh],  bh);
                    mma_f16(o, plf[hh], bh);
                    mma_f16(o, pf[hh],  bl);
                }
            }

            __syncthreads();         // all zn reads done; A tiles free for o

            #pragma unroll
            for (int hh = 0; hh < 2; ++hh) {
                #pragma unroll
                for (int cb = 0; cb < 2; ++cb) {
                    const int nb = hh * 2 + cb;
                    const int col = wn * 32 + nb * 8 + 2 * (lane & 3);
                    const float b0 = bg[col], b1 = bg[col + 1];
                    float* o = oc[hh][cb];
                    o[0] *= sigmoidf_(cg[nb][0] + b0);
                    o[1] *= sigmoidf_(cg[nb][1] + b1);
                    o[2] *= sigmoidf_(cg[nb][2] + b0);
                    o[3] *= sigmoidf_(cg[nb][3] + b1);
                    const int r = wm * 16 + (lane >> 2);
                    store_o2(smem, r,     col, o[0], o[1]);
                    store_o2(smem, r + 8, col, o[2], o[3]);
                }
            }
        }
        __syncthreads();             // o visible

        // ---------- out GEMM: o @ Wo + bo ----------
        {
            float c[4][4];
            #pragma unroll
            for (int j = 0; j < 4; ++j) { c[j][0]=0.f; c[j][1]=0.f; c[j][2]=0.f; c[j][3]=0.f; }
            gemm_dual(base, W_OFF(4), wm, wn, lane, c);

            const int r  = wm * 16 + (lane >> 2);
            const int r8 = r + 8;
            const long long grow  = (long long)(r  & 15) * PAIRS + pbase + (r  >> 4);
            const long long grow8 = (long long)(r8 & 15) * PAIRS + pbase + (r8 >> 4);
            #pragma unroll
            for (int nb = 0; nb < 4; ++nb) {
                const int col = wn * 32 + nb * 8 + 2 * (lane & 3);
                const float b0 = bo[col], b1 = bo[col + 1];
                *(float2*)&out[grow  * 128 + col] = make_float2(c[nb][0] + b0, c[nb][1] + b1);
                *(float2*)&out[grow8 * 128 + col] = make_float2(c[nb][2] + b0, c[nb][3] + b1);
            }
        }
    }
}

// =====================================================================================
extern "C" void kernel_launch(void* const* d_in, const int* in_sizes, int n_in,
                              void* d_out, int out_size)
{
    (void)in_sizes; (void)n_in; (void)out_size;
    const float* z   = (const float*)d_in[0];
    const float* lnw = (const float*)d_in[1];
    const float* lnb = (const float*)d_in[2];
    const float* Wq  = (const float*)d_in[3];
    const float* Wk  = (const float*)d_in[4];
    const float* Wv  = (const float*)d_in[5];
    const float* Wg  = (const float*)d_in[6];
    const float* bg  = (const float*)d_in[7];
    const float* Wo  = (const float*)d_in[8];
    const float* bo  = (const float*)d_in[9];
    float* out = (float*)d_out;

    cudaFuncSetAttribute(kernel_fused, cudaFuncAttributeMaxDynamicSharedMemorySize, SMEM_TOTAL);

    kernel_prep<<<5, 256>>>(Wq, Wk, Wv, Wg, Wo);
    kernel_fused<<<GRID, NT, SMEM_TOTAL>>>(z, lnw, lnb, bg, bo, out);
}

// round 13
// speedup vs baseline: 1.5145x; 1.5145x over previous
#include <cuda_runtime.h>
#include <cuda_fp16.h>
#include <cstdint>

#define PAIRS   16384
#define NBLOCKS 4096         // 16384 pairs / 4 per block-iteration
#define NT      512          // 16 warps, 1 CTA/SM (persistent)
#define GRID    152          // GB300 SM count

// ---------------- smem layout (bytes) ----------------
#define SM_A_HI  0u          // 64x128 fp16 swizzled (zn, later o_hi)
#define SM_A_LO  16384u      // zn_lo / o_lo
#define W_OFF(m) (32768u + (uint32_t)(m) * 32768u)   // 5 resident W images
#define SM_Z     196608u     // 64x128 fp32 raw z prefetch buffer (32KB)
#define SMEM_TOTAL 229376u

// ---------------- W images: 5 mats x 128x128 fp16, [n][k] ----------------
__device__ __half g_wimg[5 * 16384];

// ---------------- helpers ----------------
__device__ __forceinline__ uint32_t smem_u32(const void* p) {
    uint32_t a;
    asm("{ .reg .u64 t; cvta.to.shared.u64 t, %1; cvt.u32.u64 %0, t; }" : "=r"(a) : "l"(p));
    return a;
}
__device__ __forceinline__ float sigmoidf_(float x) { return 1.0f / (1.0f + __expf(-x)); }

__device__ __forceinline__ void ldmA4(uint32_t r[4], uint32_t addr) {
    asm volatile("ldmatrix.sync.aligned.m8n8.x4.shared.b16 {%0,%1,%2,%3}, [%4];"
                 : "=r"(r[0]), "=r"(r[1]), "=r"(r[2]), "=r"(r[3]) : "r"(addr));
}
__device__ __forceinline__ void ldmB2(uint32_t r[2], uint32_t addr) {
    asm volatile("ldmatrix.sync.aligned.m8n8.x2.shared.b16 {%0,%1}, [%2];"
                 : "=r"(r[0]), "=r"(r[1]) : "r"(addr));
}
__device__ __forceinline__ void mma_f16(float c[4], const uint32_t a[4], const uint32_t b[2]) {
    asm volatile(
        "mma.sync.aligned.m16n8k16.row.col.f32.f16.f16.f32 "
        "{%0,%1,%2,%3}, {%4,%5,%6,%7}, {%8,%9}, {%0,%1,%2,%3};"
        : "+f"(c[0]), "+f"(c[1]), "+f"(c[2]), "+f"(c[3])
        : "r"(a[0]), "r"(a[1]), "r"(a[2]), "r"(a[3]), "r"(b[0]), "r"(b[1]));
}
__device__ __forceinline__ uint32_t movm(uint32_t a) {
    uint32_t d;
    asm volatile("movmatrix.sync.aligned.m8n8.trans.b16 %0, %1;" : "=r"(d) : "r"(a));
    return d;
}
__device__ __forceinline__ void cp_async16(uint32_t dst, const void* src) {
    asm volatile("cp.async.ca.shared.global [%0], [%1], 16;" :: "r"(dst), "l"(src));
}
__device__ __forceinline__ void cp_commit() { asm volatile("cp.async.commit_group;"); }
#define CP_WAIT(n) asm volatile("cp.async.wait_group %0;" :: "n"(n))

__device__ __forceinline__ uint32_t h2bits(float x, float y) {
    __half2 h = __floats2half2_rn(x, y);
    return *(uint32_t*)&h;
}
__device__ __forceinline__ uint32_t h2res(float x, float y, uint32_t hb) {
    __half2 h = *(__half2*)&hb;
    float2 f = __half22float2(h);
    __half2 l = __floats2half2_rn(x - f.x, y - f.y);
    return *(uint32_t*)&l;
}

// =====================================================================================
// prep: round W to fp16, transpose to [n][k]
// =====================================================================================
__global__ void kernel_prep(const float* __restrict__ Wq, const float* __restrict__ Wk,
                            const float* __restrict__ Wv, const float* __restrict__ Wg,
                            const float* __restrict__ Wo)
{
    const int m = blockIdx.x;
    const float* W = (m == 0) ? Wq : (m == 1) ? Wk : (m == 2) ? Wv : (m == 3) ? Wg : Wo;
    __half* hi = g_wimg + (long long)m * 16384;
    for (int idx = threadIdx.x; idx < 16384; idx += blockDim.x) {
        const int n = idx >> 7, k = idx & 127;
        hi[n * 128 + k] = __float2half_rn(W[k * 128 + n]);
    }
}

// ---------------- building blocks ----------------
__device__ __forceinline__ void stage_img(uint32_t base, uint32_t dstOff,
                                          const __half* img, int t)
{
    #pragma unroll
    for (int it = 0; it < 4; ++it) {
        const int idx = t + it * NT;
        const uint32_t row = (uint32_t)(idx >> 4), c = (uint32_t)(idx & 15);
        cp_async16(base + dstOff + row * 256u + ((c ^ (row & 7u)) << 4),
                   img + row * 128u + c * 8u);
    }
}

// prefetch raw z tile (64 rows x 128 fp32) for pair-block pbase into SM_Z
__device__ __forceinline__ void stage_z(uint32_t base, const float* __restrict__ z,
                                        int pbase, int t)
{
    #pragma unroll
    for (int it = 0; it < 4; ++it) {
        const int idx = t + it * NT;            // 2048 chunks of 16B
        const int row = idx >> 5, c = idx & 31;
        const long long grow = (long long)(row & 15) * PAIRS + pbase + (row >> 4);
        cp_async16(base + SM_Z + (uint32_t)row * 512u + (uint32_t)c * 16u,
                   z + grow * 128 + c * 4);
    }
}

// fused single+single: cq += Ah*B0, ck += Ah*B1 (shared A loads)
__device__ __forceinline__ void gemm_qk(uint32_t base, uint32_t b0Off, uint32_t b1Off,
                                        int wm, int wn, int lane,
                                        float cq[4][4], float ck[4][4])
{
    const uint32_t arow = (uint32_t)(wm * 16 + (lane & 15));
    const uint32_t asel = (uint32_t)(lane >> 4);
    const int brow0 = wn * 32 + (lane & 7);
    const uint32_t bsel = (uint32_t)((lane >> 3) & 1);
    #pragma unroll
    for (int k = 0; k < 8; ++k) {
        uint32_t ah[4], b0[4][2], b1[4][2];
        const uint32_t c16 = (uint32_t)(k * 2) + asel;
        ldmA4(ah, base + SM_A_HI + arow * 256u + ((c16 ^ (arow & 7u)) << 4));
        #pragma unroll
        for (int nb = 0; nb < 4; ++nb) {
            const uint32_t row = (uint32_t)(brow0 + nb * 8);
            const uint32_t bc = (uint32_t)(k * 2) + bsel;
            const uint32_t off = row * 256u + ((bc ^ (row & 7u)) << 4);
            ldmB2(b0[nb], base + b0Off + off);
            ldmB2(b1[nb], base + b1Off + off);
        }
        #pragma unroll
        for (int nb = 0; nb < 4; ++nb) {
            mma_f16(cq[nb], ah, b0[nb]);
            mma_f16(ck[nb], ah, b1[nb]);
        }
    }
}

// fused dual+single: cv += (Ah+Al)*B0, cg += Ah*B1 (shared A loads)
__device__ __forceinline__ void gemm_vg(uint32_t base, uint32_t b0Off, uint32_t b1Off,
                                        int wm, int wn, int lane,
                                        float cv[4][4], float cg[4][4])
{
    const uint32_t arow = (uint32_t)(wm * 16 + (lane & 15));
    const uint32_t asel = (uint32_t)(lane >> 4);
    const int brow0 = wn * 32 + (lane & 7);
    const uint32_t bsel = (uint32_t)((lane >> 3) & 1);
    #pragma unroll
    for (int k = 0; k < 8; ++k) {
        uint32_t ah[4], al[4], b0[4][2], b1[4][2];
        const uint32_t c16 = (uint32_t)(k * 2) + asel;
        const uint32_t ad = base + arow * 256u + ((c16 ^ (arow & 7u)) << 4);
        ldmA4(ah, ad + SM_A_HI);
        ldmA4(al, ad + SM_A_LO);
        #pragma unroll
        for (int nb = 0; nb < 4; ++nb) {
            const uint32_t row = (uint32_t)(brow0 + nb * 8);
            const uint32_t bc = (uint32_t)(k * 2) + bsel;
            const uint32_t off = row * 256u + ((bc ^ (row & 7u)) << 4);
            ldmB2(b0[nb], base + b0Off + off);
            ldmB2(b1[nb], base + b1Off + off);
        }
        #pragma unroll
        for (int nb = 0; nb < 4; ++nb) {
            mma_f16(cv[nb], ah, b0[nb]);
            mma_f16(cg[nb], ah, b1[nb]);
            mma_f16(cv[nb], al, b0[nb]);
        }
    }
}

// dual pass for out GEMM: c += (Ah+Al)*B
__device__ __forceinline__ void gemm_dual(uint32_t base, uint32_t bOff, int wm, int wn,
                                          int lane, float c[4][4])
{
    const uint32_t arow = (uint32_t)(wm * 16 + (lane & 15));
    const uint32_t asel = (uint32_t)(lane >> 4);
    const int brow0 = wn * 32 + (lane & 7);
    const uint32_t bsel = (uint32_t)((lane >> 3) & 1);
    #pragma unroll
    for (int k = 0; k < 8; ++k) {
        uint32_t ah[4], al[4], b[4][2];
        const uint32_t c16 = (uint32_t)(k * 2) + asel;
        const uint32_t ad = base + arow * 256u + ((c16 ^ (arow & 7u)) << 4);
        ldmA4(ah, ad + SM_A_HI);
        ldmA4(al, ad + SM_A_LO);
        #pragma unroll
        for (int nb = 0; nb < 4; ++nb) {
            const uint32_t row = (uint32_t)(brow0 + nb * 8);
            const uint32_t bc = (uint32_t)(k * 2) + bsel;
            ldmB2(b[nb], base + bOff + row * 256u + ((bc ^ (row & 7u)) << 4));
        }
        #pragma unroll
        for (int nb = 0; nb < 4; ++nb) {
            mma_f16(c[nb], ah, b[nb]);
            mma_f16(c[nb], al, b[nb]);
        }
    }
}

// LN: split 4 floats -> hi/lo fp16 into swizzled A tiles
__device__ __forceinline__ void store_a4(char* smem, int r, int lane, float4 v)
{
    const uint32_t chunk = (uint32_t)(lane >> 1);
    const uint32_t addr = (uint32_t)r * 256u + ((chunk ^ (uint32_t)(r & 7)) << 4)
                        + (uint32_t)((lane & 1) * 8);
    const __half hx = __float2half_rn(v.x), hy = __float2half_rn(v.y);
    const __half hz = __float2half_rn(v.z), hw = __float2half_rn(v.w);
    const __half2 h01 = __halves2half2(hx, hy), h23 = __halves2half2(hz, hw);
    const __half2 l01 = __halves2half2(__float2half_rn(v.x - __half2float(hx)),
                                       __float2half_rn(v.y - __half2float(hy)));
    const __half2 l23 = __halves2half2(__float2half_rn(v.z - __half2float(hz)),
                                       __float2half_rn(v.w - __half2float(hw)));
    *(__half2*)(smem + SM_A_HI + addr)     = h01;
    *(__half2*)(smem + SM_A_HI + addr + 4) = h23;
    *(__half2*)(smem + SM_A_LO + addr)     = l01;
    *(__half2*)(smem + SM_A_LO + addr + 4) = l23;
}

// hi/lo split store of one half2 into the A tiles
__device__ __forceinline__ void store_o2(char* smem, int row, int col, float x, float y)
{
    const uint32_t chunk = (uint32_t)(col >> 3);
    const uint32_t off = (uint32_t)row * 256u + ((chunk ^ (uint32_t)(row & 7)) << 4)
                       + (uint32_t)((col & 7) * 2);
    const __half2 h = __floats2half2_rn(x, y);
    const float2 f = __half22float2(h);
    const __half2 l = __floats2half2_rn(x - f.x, y - f.y);
    *(__half2*)(smem + SM_A_HI + off) = h;
    *(__half2*)(smem + SM_A_LO + off) = l;
}

__device__ __forceinline__ const __half* wimg(int mat) {
    return g_wimg + (long long)mat * 16384;
}

// =====================================================================================
// persistent fused kernel: 5 W images resident; z software-pipelined via cp.async
// (round-11 GEMM bodies: ldmB2 B loads — the ldmX4 B variant regressed)
// 4 pairs per iteration, 16 warps; warp (wm=pair, wn=head-pair)
// =====================================================================================
__global__ __launch_bounds__(NT, 1)
void kernel_fused(const float* __restrict__ z,
                  const float* __restrict__ lnw, const float* __restrict__ lnb,
                  const float* __restrict__ bg,  const float* __restrict__ bo,
                  float* __restrict__ out)
{
    extern __shared__ char smem[];
    const uint32_t base = smem_u32(smem);

    const int t = threadIdx.x, lane = t & 31, warp = t >> 5;
    const int wm = warp >> 2, wn = warp & 3;

    // ---------- stage all 5 W images + first z tile ----------
    #pragma unroll
    for (int m = 0; m < 5; ++m)
        stage_img(base, W_OFF(m), wimg(m), t);
    stage_z(base, z, blockIdx.x * 4, t);
    cp_commit();

    const float4 lw = *(const float4*)&lnw[lane * 4];
    const float4 lb = *(const float4*)&lnb[lane * 4];

    for (int blk = blockIdx.x; blk < NBLOCKS; blk += gridDim.x) {
        const int pbase = blk * 4;
        CP_WAIT(0);                  // z tile (and W on iter 0) landed
        __syncthreads();             // also: prior iteration's A reads done

        // ---------- LayerNorm from smem z -> zn hi/lo ----------
        for (int r = warp; r < 64; r += 16) {
            const float4 zv = *(const float4*)(smem + SM_Z + (uint32_t)r * 512u
                                               + (uint32_t)lane * 16u);
            float s  = zv.x + zv.y + zv.z + zv.w;
            float s2 = zv.x*zv.x + zv.y*zv.y + zv.z*zv.z + zv.w*zv.w;
            #pragma unroll
            for (int off = 16; off > 0; off >>= 1) {
                s  += __shfl_xor_sync(0xffffffffu, s,  off);
                s2 += __shfl_xor_sync(0xffffffffu, s2, off);
            }
            const float mu   = s * (1.0f / 128.0f);
            const float var  = s2 * (1.0f / 128.0f) - mu * mu;
            const float rstd = rsqrtf(var + 1e-5f);
            float4 o;
            o.x = (zv.x - mu) * rstd * lw.x + lb.x;
            o.y = (zv.y - mu) * rstd * lw.y + lb.y;
            o.z = (zv.z - mu) * rstd * lw.z + lb.z;
            o.w = (zv.w - mu) * rstd * lw.w + lb.w;
            store_a4(smem, r, lane, o);
        }
        __syncthreads();             // zn ready; z buffer consumed

        // prefetch next iteration's z into the (now free) z buffer
        if (blk + (int)gridDim.x < NBLOCKS) {
            stage_z(base, z, (blk + gridDim.x) * 4, t);
            cp_commit();
        }

        // ---------- fused q|k -> S -> softmax -> P fragments ----------
        uint32_t pf[2][4], plf[2][4];
        {
            float cq[4][4], ck[4][4];
            #pragma unroll
            for (int j = 0; j < 4; ++j)
                #pragma unroll
                for (int q = 0; q < 4; ++q) { cq[j][q] = 0.f; ck[j][q] = 0.f; }
            gemm_qk(base, W_OFF(0), W_OFF(1), wm, wn, lane, cq, ck);

            #pragma unroll
            for (int hh = 0; hh < 2; ++hh) {
                uint32_t qf[4], kf[4];
                qf[0] = h2bits(cq[2*hh][0],   cq[2*hh][1]);
                qf[1] = h2bits(cq[2*hh][2],   cq[2*hh][3]);
                qf[2] = h2bits(cq[2*hh+1][0], cq[2*hh+1][1]);
                qf[3] = h2bits(cq[2*hh+1][2], cq[2*hh+1][3]);
                kf[0] = h2bits(ck[2*hh][0],   ck[2*hh][1]);
                kf[1] = h2bits(ck[2*hh+1][0], ck[2*hh+1][1]);
                kf[2] = h2bits(ck[2*hh][2],   ck[2*hh][3]);
                kf[3] = h2bits(ck[2*hh+1][2], ck[2*hh+1][3]);

                float s0[4] = {0.f,0.f,0.f,0.f}, s1[4] = {0.f,0.f,0.f,0.f};
                mma_f16(s0, qf, &kf[0]);
                mma_f16(s1, qf, &kf[2]);
                #pragma unroll
                for (int q = 0; q < 4; ++q) { s0[q] *= 0.25f; s1[q] *= 0.25f; }

                float mlo = fmaxf(fmaxf(s0[0], s0[1]), fmaxf(s1[0], s1[1]));
                float mhi = fmaxf(fmaxf(s0[2], s0[3]), fmaxf(s1[2], s1[3]));
                mlo = fmaxf(mlo, __shfl_xor_sync(0xffffffffu, mlo, 1));
                mlo = fmaxf(mlo, __shfl_xor_sync(0xffffffffu, mlo, 2));
                mhi = fmaxf(mhi, __shfl_xor_sync(0xffffffffu, mhi, 1));
                mhi = fmaxf(mhi, __shfl_xor_sync(0xffffffffu, mhi, 2));
                s0[0] = __expf(s0[0] - mlo); s0[1] = __expf(s0[1] - mlo);
                s1[0] = __expf(s1[0] - mlo); s1[1] = __expf(s1[1] - mlo);
                s0[2] = __expf(s0[2] - mhi); s0[3] = __expf(s0[3] - mhi);
                s1[2] = __expf(s1[2] - mhi); s1[3] = __expf(s1[3] - mhi);
                float slo = s0[0] + s0[1] + s1[0] + s1[1];
                float shi = s0[2] + s0[3] + s1[2] + s1[3];
                slo += __shfl_xor_sync(0xffffffffu, slo, 1);
                slo += __shfl_xor_sync(0xffffffffu, slo, 2);
                shi += __shfl_xor_sync(0xffffffffu, shi, 1);
                shi += __shfl_xor_sync(0xffffffffu, shi, 2);
                const float ilo = 1.0f / slo, ihi = 1.0f / shi;
                s0[0] *= ilo; s0[1] *= ilo; s1[0] *= ilo; s1[1] *= ilo;
                s0[2] *= ihi; s0[3] *= ihi; s1[2] *= ihi; s1[3] *= ihi;

                pf[hh][0] = h2bits(s0[0], s0[1]);  plf[hh][0] = h2res(s0[0], s0[1], pf[hh][0]);
                pf[hh][1] = h2bits(s0[2], s0[3]);  plf[hh][1] = h2res(s0[2], s0[3], pf[hh][1]);
                pf[hh][2] = h2bits(s1[0], s1[1]);  plf[hh][2] = h2res(s1[0], s1[1], pf[hh][2]);
                pf[hh][3] = h2bits(s1[2], s1[3]);  plf[hh][3] = h2res(s1[2], s1[3], pf[hh][3]);
            }
        }

        // ---------- fused v(dual)|g -> O = P V -> gate -> store o ----------
        float oc[2][2][4];
        {
            float cv[4][4], cg[4][4];
            #pragma unroll
            for (int j = 0; j < 4; ++j)
                #pragma unroll
                for (int q = 0; q < 4; ++q) { cv[j][q] = 0.f; cg[j][q] = 0.f; }
            gemm_vg(base, W_OFF(2), W_OFF(3), wm, wn, lane, cv, cg);

            #pragma unroll
            for (int hh = 0; hh < 2; ++hh) {
                #pragma unroll
                for (int cb = 0; cb < 2; ++cb) {
                    const int nb = hh * 2 + cb;
                    const uint32_t m0 = h2bits(cv[nb][0], cv[nb][1]);
                    const uint32_t m1 = h2bits(cv[nb][2], cv[nb][3]);
                    const uint32_t r0 = h2res(cv[nb][0], cv[nb][1], m0);
                    const uint32_t r1 = h2res(cv[nb][2], cv[nb][3], m1);
                    uint32_t bh[2], bl[2];
                    bh[0] = movm(m0); bh[1] = movm(m1);
                    bl[0] = movm(r0); bl[1] = movm(r1);
                    float* o = oc[hh][cb];
                    o[0] = 0.f; o[1] = 0.f; o[2] = 0.f; o[3] = 0.f;
                    mma_f16(o, pf[hh],  bh);
                    mma_f16(o, plf[hh], bh);
                    mma_f16(o, pf[hh],  bl);
                }
            }

            __syncthreads();         // all zn reads done; A tiles free for o

            #pragma unroll
            for (int hh = 0; hh < 2; ++hh) {
                #pragma unroll
                for (int cb = 0; cb < 2; ++cb) {
                    const int nb = hh * 2 + cb;
                    const int col = wn * 32 + nb * 8 + 2 * (lane & 3);
                    const float b0 = bg[col], b1 = bg[col + 1];
                    float* o = oc[hh][cb];
                    o[0] *= sigmoidf_(cg[nb][0] + b0);
                    o[1] *= sigmoidf_(cg[nb][1] + b1);
                    o[2] *= sigmoidf_(cg[nb][2] + b0);
                    o[3] *= sigmoidf_(cg[nb][3] + b1);
                    const int r = wm * 16 + (lane >> 2);
                    store_o2(smem, r,     col, o[0], o[1]);
                    store_o2(smem, r + 8, col, o[2], o[3]);
                }
            }
        }
        __syncthreads();             // o visible

        // ---------- out GEMM: o @ Wo + bo ----------
        {
            float c[4][4];
            #pragma unroll
            for (int j = 0; j < 4; ++j) { c[j][0]=0.f; c[j][1]=0.f; c[j][2]=0.f; c[j][3]=0.f; }
            gemm_dual(base, W_OFF(4), wm, wn, lane, c);

            const int r  = wm * 16 + (lane >> 2);
            const int r8 = r + 8;
            const long long grow  = (long long)(r  & 15) * PAIRS + pbase + (r  >> 4);
            const long long grow8 = (long long)(r8 & 15) * PAIRS + pbase + (r8 >> 4);
            #pragma unroll
            for (int nb = 0; nb < 4; ++nb) {
                const int col = wn * 32 + nb * 8 + 2 * (lane & 3);
                const float b0 = bo[col], b1 = bo[col + 1];
                *(float2*)&out[grow  * 128 + col] = make_float2(c[nb][0] + b0, c[nb][1] + b1);
                *(float2*)&out[grow8 * 128 + col] = make_float2(c[nb][2] + b0, c[nb][3] + b1);
            }
        }
    }
}

// =====================================================================================
extern "C" void kernel_launch(void* const* d_in, const int* in_sizes, int n_in,
                              void* d_out, int out_size)
{
    (void)in_sizes; (void)n_in; (void)out_size;
    const float* z   = (const float*)d_in[0];
    const float* lnw = (const float*)d_in[1];
    const float* lnb = (const float*)d_in[2];
    const float* Wq  = (const float*)d_in[3];
    const float* Wk  = (const float*)d_in[4];
    const float* Wv  = (const float*)d_in[5];
    const float* Wg  = (const float*)d_in[6];
    const float* bg  = (const float*)d_in[7];
    const float* Wo  = (const float*)d_in[8];
    const float* bo  = (const float*)d_in[9];
    float* out = (float*)d_out;

    cudaFuncSetAttribute(kernel_fused, cudaFuncAttributeMaxDynamicSharedMemorySize, SMEM_TOTAL);

    kernel_prep<<<5, 256>>>(Wq, Wk, Wv, Wg, Wo);
    kernel_fused<<<GRID, NT, SMEM_TOTAL>>>(z, lnw, lnb, bg, bo, out);
}

// round 14
// speedup vs baseline: 1.6555x; 1.0931x over previous
#include <cuda_runtime.h>
#include <cuda_fp16.h>
#include <cstdint>

#define PAIRS   16384
#define NBLOCKS 4096         // 16384 pairs / 4 per block-iteration
#define NT      512          // 16 warps, 1 CTA/SM (persistent)
#define GRID    152          // GB300 SM count

// ---------------- smem layout (bytes) ----------------
#define SM_A_HI  0u          // 64x128 fp16 swizzled (zn, later o)  -- hi only now
#define W_OFF(m) (16384u + (uint32_t)(m) * 32768u)   // 5 resident W images
#define SM_Z     180224u     // 64x128 fp32 raw z prefetch buffer (32KB)
#define SMEM_TOTAL 212992u

// ---------------- W images: 5 mats x 128x128 fp16, [n][k] ----------------
__device__ __half g_wimg[5 * 16384];

// ---------------- helpers ----------------
__device__ __forceinline__ uint32_t smem_u32(const void* p) {
    uint32_t a;
    asm("{ .reg .u64 t; cvta.to.shared.u64 t, %1; cvt.u32.u64 %0, t; }" : "=r"(a) : "l"(p));
    return a;
}
__device__ __forceinline__ float sigmoidf_(float x) { return 1.0f / (1.0f + __expf(-x)); }

__device__ __forceinline__ void ldmA4(uint32_t r[4], uint32_t addr) {
    asm volatile("ldmatrix.sync.aligned.m8n8.x4.shared.b16 {%0,%1,%2,%3}, [%4];"
                 : "=r"(r[0]), "=r"(r[1]), "=r"(r[2]), "=r"(r[3]) : "r"(addr));
}
__device__ __forceinline__ void ldmB2(uint32_t r[2], uint32_t addr) {
    asm volatile("ldmatrix.sync.aligned.m8n8.x2.shared.b16 {%0,%1}, [%2];"
                 : "=r"(r[0]), "=r"(r[1]) : "r"(addr));
}
__device__ __forceinline__ void mma_f16(float c[4], const uint32_t a[4], const uint32_t b[2]) {
    asm volatile(
        "mma.sync.aligned.m16n8k16.row.col.f32.f16.f16.f32 "
        "{%0,%1,%2,%3}, {%4,%5,%6,%7}, {%8,%9}, {%0,%1,%2,%3};"
        : "+f"(c[0]), "+f"(c[1]), "+f"(c[2]), "+f"(c[3])
        : "r"(a[0]), "r"(a[1]), "r"(a[2]), "r"(a[3]), "r"(b[0]), "r"(b[1]));
}
__device__ __forceinline__ uint32_t movm(uint32_t a) {
    uint32_t d;
    asm volatile("movmatrix.sync.aligned.m8n8.trans.b16 %0, %1;" : "=r"(d) : "r"(a));
    return d;
}
__device__ __forceinline__ void cp_async16(uint32_t dst, const void* src) {
    asm volatile("cp.async.ca.shared.global [%0], [%1], 16;" :: "r"(dst), "l"(src));
}
__device__ __forceinline__ void cp_commit() { asm volatile("cp.async.commit_group;"); }
#define CP_WAIT(n) asm volatile("cp.async.wait_group %0;" :: "n"(n))

__device__ __forceinline__ uint32_t h2bits(float x, float y) {
    __half2 h = __floats2half2_rn(x, y);
    return *(uint32_t*)&h;
}
__device__ __forceinline__ uint32_t h2res(float x, float y, uint32_t hb) {
    __half2 h = *(__half2*)&hb;
    float2 f = __half22float2(h);
    __half2 l = __floats2half2_rn(x - f.x, y - f.y);
    return *(uint32_t*)&l;
}

// =====================================================================================
// prep: round W to fp16, transpose to [n][k]
// =====================================================================================
__global__ void kernel_prep(const float* __restrict__ Wq, const float* __restrict__ Wk,
                            const float* __restrict__ Wv, const float* __restrict__ Wg,
                            const float* __restrict__ Wo)
{
    const int m = blockIdx.x;
    const float* W = (m == 0) ? Wq : (m == 1) ? Wk : (m == 2) ? Wv : (m == 3) ? Wg : Wo;
    __half* hi = g_wimg + (long long)m * 16384;
    for (int idx = threadIdx.x; idx < 16384; idx += blockDim.x) {
        const int n = idx >> 7, k = idx & 127;
        hi[n * 128 + k] = __float2half_rn(W[k * 128 + n]);
    }
}

// ---------------- building blocks ----------------
__device__ __forceinline__ void stage_img(uint32_t base, uint32_t dstOff,
                                          const __half* img, int t)
{
    #pragma unroll
    for (int it = 0; it < 4; ++it) {
        const int idx = t + it * NT;
        const uint32_t row = (uint32_t)(idx >> 4), c = (uint32_t)(idx & 15);
        cp_async16(base + dstOff + row * 256u + ((c ^ (row & 7u)) << 4),
                   img + row * 128u + c * 8u);
    }
}

// prefetch raw z tile (64 rows x 128 fp32) for pair-block pbase into SM_Z
__device__ __forceinline__ void stage_z(uint32_t base, const float* __restrict__ z,
                                        int pbase, int t)
{
    #pragma unroll
    for (int it = 0; it < 4; ++it) {
        const int idx = t + it * NT;            // 2048 chunks of 16B
        const int row = idx >> 5, c = idx & 31;
        const long long grow = (long long)(row & 15) * PAIRS + pbase + (row >> 4);
        cp_async16(base + SM_Z + (uint32_t)row * 512u + (uint32_t)c * 16u,
                   z + grow * 128 + c * 4);
    }
}

// fused single+single: c0 += Ah*B0, c1 += Ah*B1 (shared A loads)
__device__ __forceinline__ void gemm_pair(uint32_t base, uint32_t b0Off, uint32_t b1Off,
                                          int wm, int wn, int lane,
                                          float c0[4][4], float c1[4][4])
{
    const uint32_t arow = (uint32_t)(wm * 16 + (lane & 15));
    const uint32_t asel = (uint32_t)(lane >> 4);
    const int brow0 = wn * 32 + (lane & 7);
    const uint32_t bsel = (uint32_t)((lane >> 3) & 1);
    #pragma unroll
    for (int k = 0; k < 8; ++k) {
        uint32_t ah[4], b0[4][2], b1[4][2];
        const uint32_t c16 = (uint32_t)(k * 2) + asel;
        ldmA4(ah, base + SM_A_HI + arow * 256u + ((c16 ^ (arow & 7u)) << 4));
        #pragma unroll
        for (int nb = 0; nb < 4; ++nb) {
            const uint32_t row = (uint32_t)(brow0 + nb * 8);
            const uint32_t bc = (uint32_t)(k * 2) + bsel;
            const uint32_t off = row * 256u + ((bc ^ (row & 7u)) << 4);
            ldmB2(b0[nb], base + b0Off + off);
            ldmB2(b1[nb], base + b1Off + off);
        }
        #pragma unroll
        for (int nb = 0; nb < 4; ++nb) {
            mma_f16(c0[nb], ah, b0[nb]);
            mma_f16(c1[nb], ah, b1[nb]);
        }
    }
}

// single-image single-pass for out GEMM: c += Ah*B
__device__ __forceinline__ void gemm_single(uint32_t base, uint32_t bOff, int wm, int wn,
                                            int lane, float c[4][4])
{
    const uint32_t arow = (uint32_t)(wm * 16 + (lane & 15));
    const uint32_t asel = (uint32_t)(lane >> 4);
    const int brow0 = wn * 32 + (lane & 7);
    const uint32_t bsel = (uint32_t)((lane >> 3) & 1);
    #pragma unroll
    for (int k = 0; k < 8; ++k) {
        uint32_t ah[4], b[4][2];
        const uint32_t c16 = (uint32_t)(k * 2) + asel;
        ldmA4(ah, base + SM_A_HI + arow * 256u + ((c16 ^ (arow & 7u)) << 4));
        #pragma unroll
        for (int nb = 0; nb < 4; ++nb) {
            const uint32_t row = (uint32_t)(brow0 + nb * 8);
            const uint32_t bc = (uint32_t)(k * 2) + bsel;
            ldmB2(b[nb], base + bOff + row * 256u + ((bc ^ (row & 7u)) << 4));
        }
        #pragma unroll
        for (int nb = 0; nb < 4; ++nb)
            mma_f16(c[nb], ah, b[nb]);
    }
}

// LN: store 4 floats as fp16 (hi only) into swizzled A tile
__device__ __forceinline__ void store_a4(char* smem, int r, int lane, float4 v)
{
    const uint32_t chunk = (uint32_t)(lane >> 1);
    const uint32_t addr = (uint32_t)r * 256u + ((chunk ^ (uint32_t)(r & 7)) << 4)
                        + (uint32_t)((lane & 1) * 8);
    const __half2 h01 = __floats2half2_rn(v.x, v.y);
    const __half2 h23 = __floats2half2_rn(v.z, v.w);
    *(__half2*)(smem + SM_A_HI + addr)     = h01;
    *(__half2*)(smem + SM_A_HI + addr + 4) = h23;
}

// store one half2 (hi only) into the A tile
__device__ __forceinline__ void store_o2(char* smem, int row, int col, float x, float y)
{
    const uint32_t chunk = (uint32_t)(col >> 3);
    const uint32_t off = (uint32_t)row * 256u + ((chunk ^ (uint32_t)(row & 7)) << 4)
                       + (uint32_t)((col & 7) * 2);
    *(__half2*)(smem + SM_A_HI + off) = __floats2half2_rn(x, y);
}

__device__ __forceinline__ const __half* wimg(int mat) {
    return g_wimg + (long long)mat * 16384;
}

// =====================================================================================
// persistent fused kernel: 5 W images resident; z software-pipelined via cp.async
// all projections single-pass fp16 A; O=PV keeps 3-term (v hi/lo) guard
// 4 pairs per iteration, 16 warps; warp (wm=pair, wn=head-pair)
// =====================================================================================
__global__ __launch_bounds__(NT, 1)
void kernel_fused(const float* __restrict__ z,
                  const float* __restrict__ lnw, const float* __restrict__ lnb,
                  const float* __restrict__ bg,  const float* __restrict__ bo,
                  float* __restrict__ out)
{
    extern __shared__ char smem[];
    const uint32_t base = smem_u32(smem);

    const int t = threadIdx.x, lane = t & 31, warp = t >> 5;
    const int wm = warp >> 2, wn = warp & 3;

    // ---------- stage all 5 W images + first z tile ----------
    #pragma unroll
    for (int m = 0; m < 5; ++m)
        stage_img(base, W_OFF(m), wimg(m), t);
    stage_z(base, z, blockIdx.x * 4, t);
    cp_commit();

    const float4 lw = *(const float4*)&lnw[lane * 4];
    const float4 lb = *(const float4*)&lnb[lane * 4];

    for (int blk = blockIdx.x; blk < NBLOCKS; blk += gridDim.x) {
        const int pbase = blk * 4;
        CP_WAIT(0);                  // z tile (and W on iter 0) landed
        __syncthreads();             // also: prior iteration's A reads done

        // ---------- LayerNorm from smem z -> zn (fp16 hi only) ----------
        for (int r = warp; r < 64; r += 16) {
            const float4 zv = *(const float4*)(smem + SM_Z + (uint32_t)r * 512u
                                               + (uint32_t)lane * 16u);
            float s  = zv.x + zv.y + zv.z + zv.w;
            float s2 = zv.x*zv.x + zv.y*zv.y + zv.z*zv.z + zv.w*zv.w;
            #pragma unroll
            for (int off = 16; off > 0; off >>= 1) {
                s  += __shfl_xor_sync(0xffffffffu, s,  off);
                s2 += __shfl_xor_sync(0xffffffffu, s2, off);
            }
            const float mu   = s * (1.0f / 128.0f);
            const float var  = s2 * (1.0f / 128.0f) - mu * mu;
            const float rstd = rsqrtf(var + 1e-5f);
            float4 o;
            o.x = (zv.x - mu) * rstd * lw.x + lb.x;
            o.y = (zv.y - mu) * rstd * lw.y + lb.y;
            o.z = (zv.z - mu) * rstd * lw.z + lb.z;
            o.w = (zv.w - mu) * rstd * lw.w + lb.w;
            store_a4(smem, r, lane, o);
        }
        __syncthreads();             // zn ready; z buffer consumed

        // prefetch next iteration's z into the (now free) z buffer
        if (blk + (int)gridDim.x < NBLOCKS) {
            stage_z(base, z, (blk + gridDim.x) * 4, t);
            cp_commit();
        }

        // ---------- fused q|k -> S -> softmax -> P fragments ----------
        uint32_t pf[2][4], plf[2][4];
        {
            float cq[4][4], ck[4][4];
            #pragma unroll
            for (int j = 0; j < 4; ++j)
                #pragma unroll
                for (int q = 0; q < 4; ++q) { cq[j][q] = 0.f; ck[j][q] = 0.f; }
            gemm_pair(base, W_OFF(0), W_OFF(1), wm, wn, lane, cq, ck);

            #pragma unroll
            for (int hh = 0; hh < 2; ++hh) {
                uint32_t qf[4], kf[4];
                qf[0] = h2bits(cq[2*hh][0],   cq[2*hh][1]);
                qf[1] = h2bits(cq[2*hh][2],   cq[2*hh][3]);
                qf[2] = h2bits(cq[2*hh+1][0], cq[2*hh+1][1]);
                qf[3] = h2bits(cq[2*hh+1][2], cq[2*hh+1][3]);
                kf[0] = h2bits(ck[2*hh][0],   ck[2*hh][1]);
                kf[1] = h2bits(ck[2*hh+1][0], ck[2*hh+1][1]);
                kf[2] = h2bits(ck[2*hh][2],   ck[2*hh][3]);
                kf[3] = h2bits(ck[2*hh+1][2], ck[2*hh+1][3]);

                float s0[4] = {0.f,0.f,0.f,0.f}, s1[4] = {0.f,0.f,0.f,0.f};
                mma_f16(s0, qf, &kf[0]);
                mma_f16(s1, qf, &kf[2]);
                #pragma unroll
                for (int q = 0; q < 4; ++q) { s0[q] *= 0.25f; s1[q] *= 0.25f; }

                float mlo = fmaxf(fmaxf(s0[0], s0[1]), fmaxf(s1[0], s1[1]));
                float mhi = fmaxf(fmaxf(s0[2], s0[3]), fmaxf(s1[2], s1[3]));
                mlo = fmaxf(mlo, __shfl_xor_sync(0xffffffffu, mlo, 1));
                mlo = fmaxf(mlo, __shfl_xor_sync(0xffffffffu, mlo, 2));
                mhi = fmaxf(mhi, __shfl_xor_sync(0xffffffffu, mhi, 1));
                mhi = fmaxf(mhi, __shfl_xor_sync(0xffffffffu, mhi, 2));
                s0[0] = __expf(s0[0] - mlo); s0[1] = __expf(s0[1] - mlo);
                s1[0] = __expf(s1[0] - mlo); s1[1] = __expf(s1[1] - mlo);
                s0[2] = __expf(s0[2] - mhi); s0[3] = __expf(s0[3] - mhi);
                s1[2] = __expf(s1[2] - mhi); s1[3] = __expf(s1[3] - mhi);
                float slo = s0[0] + s0[1] + s1[0] + s1[1];
                float shi = s0[2] + s0[3] + s1[2] + s1[3];
                slo += __shfl_xor_sync(0xffffffffu, slo, 1);
                slo += __shfl_xor_sync(0xffffffffu, slo, 2);
                shi += __shfl_xor_sync(0xffffffffu, shi, 1);
                shi += __shfl_xor_sync(0xffffffffu, shi, 2);
                const float ilo = 1.0f / slo, ihi = 1.0f / shi;
                s0[0] *= ilo; s0[1] *= ilo; s1[0] *= ilo; s1[1] *= ilo;
                s0[2] *= ihi; s0[3] *= ihi; s1[2] *= ihi; s1[3] *= ihi;

                pf[hh][0] = h2bits(s0[0], s0[1]);  plf[hh][0] = h2res(s0[0], s0[1], pf[hh][0]);
                pf[hh][1] = h2bits(s0[2], s0[3]);  plf[hh][1] = h2res(s0[2], s0[3], pf[hh][1]);
                pf[hh][2] = h2bits(s1[0], s1[1]);  plf[hh][2] = h2res(s1[0], s1[1], pf[hh][2]);
                pf[hh][3] = h2bits(s1[2], s1[3]);  plf[hh][3] = h2res(s1[2], s1[3], pf[hh][3]);
            }
        }

        // ---------- fused v|g (both single-pass) -> O = P V (3-term) -> gate ----------
        float oc[2][2][4];
        {
            float cv[4][4], cg[4][4];
            #pragma unroll
            for (int j = 0; j < 4; ++j)
                #pragma unroll
                for (int q = 0; q < 4; ++q) { cv[j][q] = 0.f; cg[j][q] = 0.f; }
            gemm_pair(base, W_OFF(2), W_OFF(3), wm, wn, lane, cv, cg);

            #pragma unroll
            for (int hh = 0; hh < 2; ++hh) {
                #pragma unroll
                for (int cb = 0; cb < 2; ++cb) {
                    const int nb = hh * 2 + cb;
                    const uint32_t m0 = h2bits(cv[nb][0], cv[nb][1]);
                    const uint32_t m1 = h2bits(cv[nb][2], cv[nb][3]);
                    const uint32_t r0 = h2res(cv[nb][0], cv[nb][1], m0);
                    const uint32_t r1 = h2res(cv[nb][2], cv[nb][3], m1);
                    uint32_t bh[2], bl[2];
                    bh[0] = movm(m0); bh[1] = movm(m1);
                    bl[0] = movm(r0); bl[1] = movm(r1);
                    float* o = oc[hh][cb];
                    o[0] = 0.f; o[1] = 0.f; o[2] = 0.f; o[3] = 0.f;
                    mma_f16(o, pf[hh],  bh);
                    mma_f16(o, plf[hh], bh);
                    mma_f16(o, pf[hh],  bl);
                }
            }

            __syncthreads();         // all zn reads done; A tile free for o

            #pragma unroll
            for (int hh = 0; hh < 2; ++hh) {
                #pragma unroll
                for (int cb = 0; cb < 2; ++cb) {
                    const int nb = hh * 2 + cb;
                    const int col = wn * 32 + nb * 8 + 2 * (lane & 3);
                    const float b0 = bg[col], b1 = bg[col + 1];
                    float* o = oc[hh][cb];
                    o[0] *= sigmoidf_(cg[nb][0] + b0);
                    o[1] *= sigmoidf_(cg[nb][1] + b1);
                    o[2] *= sigmoidf_(cg[nb][2] + b0);
                    o[3] *= sigmoidf_(cg[nb][3] + b1);
                    const int r = wm * 16 + (lane >> 2);
                    store_o2(smem, r,     col, o[0], o[1]);
                    store_o2(smem, r + 8, col, o[2], o[3]);
                }
            }
        }
        __syncthreads();             // o visible

        // ---------- out GEMM (single-pass): o @ Wo + bo ----------
        {
            float c[4][4];
            #pragma unroll
            for (int j = 0; j < 4; ++j) { c[j][0]=0.f; c[j][1]=0.f; c[j][2]=0.f; c[j][3]=0.f; }
            gemm_single(base, W_OFF(4), wm, wn, lane, c);

            const int r  = wm * 16 + (lane >> 2);
            const int r8 = r + 8;
            const long long grow  = (long long)(r  & 15) * PAIRS + pbase + (r  >> 4);
            const long long grow8 = (long long)(r8 & 15) * PAIRS + pbase + (r8 >> 4);
            #pragma unroll
            for (int nb = 0; nb < 4; ++nb) {
                const int col = wn * 32 + nb * 8 + 2 * (lane & 3);
                const float b0 = bo[col], b1 = bo[col + 1];
                *(float2*)&out[grow  * 128 + col] = make_float2(c[nb][0] + b0, c[nb][1] + b1);
                *(float2*)&out[grow8 * 128 + col] = make_float2(c[nb][2] + b0, c[nb][3] + b1);
            }
        }
    }
}

// =====================================================================================
extern "C" void kernel_launch(void* const* d_in, const int* in_sizes, int n_in,
                              void* d_out, int out_size)
{
    (void)in_sizes; (void)n_in; (void)out_size;
    const float* z   = (const float*)d_in[0];
    const float* lnw = (const float*)d_in[1];
    const float* lnb = (const float*)d_in[2];
    const float* Wq  = (const float*)d_in[3];
    const float* Wk  = (const float*)d_in[4];
    const float* Wv  = (const float*)d_in[5];
    const float* Wg  = (const float*)d_in[6];
    const float* bg  = (const float*)d_in[7];
    const float* Wo  = (const float*)d_in[8];
    const float* bo  = (const float*)d_in[9];
    float* out = (float*)d_out;

    cudaFuncSetAttribute(kernel_fused, cudaFuncAttributeMaxDynamicSharedMemorySize, SMEM_TOTAL);

    kernel_prep<<<5, 256>>>(Wq, Wk, Wv, Wg, Wo);
    kernel_fused<<<GRID, NT, SMEM_TOTAL>>>(z, lnw, lnb, bg, bo, out);
}

// round 15
// speedup vs baseline: 1.7018x; 1.0279x over previous
#include <cuda_runtime.h>
#include <cuda_fp16.h>
#include <cstdint>

#define PAIRS   16384
#define NBLOCKS 4096         // 16384 pairs / 4 per block-iteration
#define NT      512          // 16 warps, 1 CTA/SM (persistent)
#define GRID    152          // GB300 SM count

// ---------------- smem layout (bytes) ----------------
#define SM_A_HI  0u          // 64x128 fp16 swizzled zn tile (hi only)
#define W_OFF(m) (16384u + (uint32_t)(m) * 32768u)   // 5 resident W images -> ends 180224
#define SM_O     180224u     // 64x128 fp16 swizzled o tile (16KB)
#define SM_Z     196608u     // 64x128 fp32 raw z prefetch buffer (32KB)
#define SMEM_TOTAL 229376u

// ---------------- W images: 5 mats x 128x128 fp16, [n][k] ----------------
__device__ __half g_wimg[5 * 16384];

// ---------------- helpers ----------------
__device__ __forceinline__ uint32_t smem_u32(const void* p) {
    uint32_t a;
    asm("{ .reg .u64 t; cvta.to.shared.u64 t, %1; cvt.u32.u64 %0, t; }" : "=r"(a) : "l"(p));
    return a;
}
__device__ __forceinline__ float sigmoidf_(float x) { return 1.0f / (1.0f + __expf(-x)); }

__device__ __forceinline__ void ldmA4(uint32_t r[4], uint32_t addr) {
    asm volatile("ldmatrix.sync.aligned.m8n8.x4.shared.b16 {%0,%1,%2,%3}, [%4];"
                 : "=r"(r[0]), "=r"(r[1]), "=r"(r[2]), "=r"(r[3]) : "r"(addr));
}
__device__ __forceinline__ void ldmB2(uint32_t r[2], uint32_t addr) {
    asm volatile("ldmatrix.sync.aligned.m8n8.x2.shared.b16 {%0,%1}, [%2];"
                 : "=r"(r[0]), "=r"(r[1]) : "r"(addr));
}
__device__ __forceinline__ void mma_f16(float c[4], const uint32_t a[4], const uint32_t b[2]) {
    asm volatile(
        "mma.sync.aligned.m16n8k16.row.col.f32.f16.f16.f32 "
        "{%0,%1,%2,%3}, {%4,%5,%6,%7}, {%8,%9}, {%0,%1,%2,%3};"
        : "+f"(c[0]), "+f"(c[1]), "+f"(c[2]), "+f"(c[3])
        : "r"(a[0]), "r"(a[1]), "r"(a[2]), "r"(a[3]), "r"(b[0]), "r"(b[1]));
}
__device__ __forceinline__ uint32_t movm(uint32_t a) {
    uint32_t d;
    asm volatile("movmatrix.sync.aligned.m8n8.trans.b16 %0, %1;" : "=r"(d) : "r"(a));
    return d;
}
__device__ __forceinline__ void cp_async16(uint32_t dst, const void* src) {
    asm volatile("cp.async.ca.shared.global [%0], [%1], 16;" :: "r"(dst), "l"(src));
}
__device__ __forceinline__ void cp_commit() { asm volatile("cp.async.commit_group;"); }
#define CP_WAIT(n) asm volatile("cp.async.wait_group %0;" :: "n"(n))

__device__ __forceinline__ uint32_t h2bits(float x, float y) {
    __half2 h = __floats2half2_rn(x, y);
    return *(uint32_t*)&h;
}
__device__ __forceinline__ uint32_t h2res(float x, float y, uint32_t hb) {
    __half2 h = *(__half2*)&hb;
    float2 f = __half22float2(h);
    __half2 l = __floats2half2_rn(x - f.x, y - f.y);
    return *(uint32_t*)&l;
}

// =====================================================================================
// prep: round W to fp16, transpose to [n][k]; fold 0.25 (1/sqrt(C)) into Wq (exact)
// =====================================================================================
__global__ void kernel_prep(const float* __restrict__ Wq, const float* __restrict__ Wk,
                            const float* __restrict__ Wv, const float* __restrict__ Wg,
                            const float* __restrict__ Wo)
{
    const int m = blockIdx.x;
    const float* W = (m == 0) ? Wq : (m == 1) ? Wk : (m == 2) ? Wv : (m == 3) ? Wg : Wo;
    const float scale = (m == 0) ? 0.25f : 1.0f;
    __half* hi = g_wimg + (long long)m * 16384;
    for (int idx = threadIdx.x; idx < 16384; idx += blockDim.x) {
        const int n = idx >> 7, k = idx & 127;
        hi[n * 128 + k] = __float2half_rn(W[k * 128 + n] * scale);
    }
}

// ---------------- building blocks ----------------
__device__ __forceinline__ void stage_img(uint32_t base, uint32_t dstOff,
                                          const __half* img, int t)
{
    #pragma unroll
    for (int it = 0; it < 4; ++it) {
        const int idx = t + it * NT;
        const uint32_t row = (uint32_t)(idx >> 4), c = (uint32_t)(idx & 15);
        cp_async16(base + dstOff + row * 256u + ((c ^ (row & 7u)) << 4),
                   img + row * 128u + c * 8u);
    }
}

// prefetch raw z tile (64 rows x 128 fp32) for pair-block pbase into SM_Z.
// thread-chunk map aliases the LN read map exactly (thread t restages what it LN'd).
__device__ __forceinline__ void stage_z(uint32_t base, const float* __restrict__ z,
                                        int pbase, int t)
{
    #pragma unroll
    for (int it = 0; it < 4; ++it) {
        const int idx = t + it * NT;            // 2048 chunks of 16B
        const int row = idx >> 5, c = idx & 31;
        const long long grow = (long long)(row & 15) * PAIRS + pbase + (row >> 4);
        cp_async16(base + SM_Z + (uint32_t)row * 512u + (uint32_t)c * 16u,
                   z + grow * 128 + c * 4);
    }
}

// LN for one pair-block: reads SM_Z, writes fp16 zn into A tile (hi only)
__device__ __forceinline__ void layernorm_block(char* smem, int warp, int lane,
                                                float4 lw, float4 lb)
{
    for (int r = warp; r < 64; r += 16) {
        const float4 zv = *(const float4*)(smem + SM_Z + (uint32_t)r * 512u
                                           + (uint32_t)lane * 16u);
        float s  = zv.x + zv.y + zv.z + zv.w;
        float s2 = zv.x*zv.x + zv.y*zv.y + zv.z*zv.z + zv.w*zv.w;
        #pragma unroll
        for (int off = 16; off > 0; off >>= 1) {
            s  += __shfl_xor_sync(0xffffffffu, s,  off);
            s2 += __shfl_xor_sync(0xffffffffu, s2, off);
        }
        const float mu   = s * (1.0f / 128.0f);
        const float var  = s2 * (1.0f / 128.0f) - mu * mu;
        const float rstd = rsqrtf(var + 1e-5f);
        float4 o;
        o.x = (zv.x - mu) * rstd * lw.x + lb.x;
        o.y = (zv.y - mu) * rstd * lw.y + lb.y;
        o.z = (zv.z - mu) * rstd * lw.z + lb.z;
        o.w = (zv.w - mu) * rstd * lw.w + lb.w;
        const uint32_t chunk = (uint32_t)(lane >> 1);
        const uint32_t addr = (uint32_t)r * 256u + ((chunk ^ (uint32_t)(r & 7)) << 4)
                            + (uint32_t)((lane & 1) * 8);
        *(__half2*)(smem + SM_A_HI + addr)     = __floats2half2_rn(o.x, o.y);
        *(__half2*)(smem + SM_A_HI + addr + 4) = __floats2half2_rn(o.z, o.w);
    }
}

// fused single+single: c0 += A*B0, c1 += A*B1 (shared A loads from aOff tile)
__device__ __forceinline__ void gemm_pair(uint32_t base, uint32_t b0Off, uint32_t b1Off,
                                          int wm, int wn, int lane,
                                          float c0[4][4], float c1[4][4])
{
    const uint32_t arow = (uint32_t)(wm * 16 + (lane & 15));
    const uint32_t asel = (uint32_t)(lane >> 4);
    const int brow0 = wn * 32 + (lane & 7);
    const uint32_t bsel = (uint32_t)((lane >> 3) & 1);
    #pragma unroll
    for (int k = 0; k < 8; ++k) {
        uint32_t ah[4], b0[4][2], b1[4][2];
        const uint32_t c16 = (uint32_t)(k * 2) + asel;
        ldmA4(ah, base + SM_A_HI + arow * 256u + ((c16 ^ (arow & 7u)) << 4));
        #pragma unroll
        for (int nb = 0; nb < 4; ++nb) {
            const uint32_t row = (uint32_t)(brow0 + nb * 8);
            const uint32_t bc = (uint32_t)(k * 2) + bsel;
            const uint32_t off = row * 256u + ((bc ^ (row & 7u)) << 4);
            ldmB2(b0[nb], base + b0Off + off);
            ldmB2(b1[nb], base + b1Off + off);
        }
        #pragma unroll
        for (int nb = 0; nb < 4; ++nb) {
            mma_f16(c0[nb], ah, b0[nb]);
            mma_f16(c1[nb], ah, b1[nb]);
        }
    }
}

// single-image single-pass GEMM with A tile at aOff: c += A*B
__device__ __forceinline__ void gemm_single(uint32_t base, uint32_t aOff, uint32_t bOff,
                                            int wm, int wn, int lane, float c[4][4])
{
    const uint32_t arow = (uint32_t)(wm * 16 + (lane & 15));
    const uint32_t asel = (uint32_t)(lane >> 4);
    const int brow0 = wn * 32 + (lane & 7);
    const uint32_t bsel = (uint32_t)((lane >> 3) & 1);
    #pragma unroll
    for (int k = 0; k < 8; ++k) {
        uint32_t ah[4], b[4][2];
        const uint32_t c16 = (uint32_t)(k * 2) + asel;
        ldmA4(ah, base + aOff + arow * 256u + ((c16 ^ (arow & 7u)) << 4));
        #pragma unroll
        for (int nb = 0; nb < 4; ++nb) {
            const uint32_t row = (uint32_t)(brow0 + nb * 8);
            const uint32_t bc = (uint32_t)(k * 2) + bsel;
            ldmB2(b[nb], base + bOff + row * 256u + ((bc ^ (row & 7u)) << 4));
        }
        #pragma unroll
        for (int nb = 0; nb < 4; ++nb)
            mma_f16(c[nb], ah, b[nb]);
    }
}

// store one half2 (hi only) into the o tile
__device__ __forceinline__ void store_o2(char* smem, int row, int col, float x, float y)
{
    const uint32_t chunk = (uint32_t)(col >> 3);
    const uint32_t off = (uint32_t)row * 256u + ((chunk ^ (uint32_t)(row & 7)) << 4)
                       + (uint32_t)((col & 7) * 2);
    *(__half2*)(smem + SM_O + off) = __floats2half2_rn(x, y);
}

__device__ __forceinline__ const __half* wimg(int mat) {
    return g_wimg + (long long)mat * 16384;
}

// =====================================================================================
// persistent fused kernel, software-pipelined:
//   qk -> vg/OPV/gate -> sync -> { o-store || LN_next || z-prefetch } -> sync -> outGEMM
// 4 pairs per iteration, 16 warps; warp (wm=pair, wn=head-pair); 2 barriers/iter
// =====================================================================================
__global__ __launch_bounds__(NT, 1)
void kernel_fused(const float* __restrict__ z,
                  const float* __restrict__ lnw, const float* __restrict__ lnb,
                  const float* __restrict__ bg,  const float* __restrict__ bo,
                  float* __restrict__ out)
{
    extern __shared__ char smem[];
    const uint32_t base = smem_u32(smem);

    const int t = threadIdx.x, lane = t & 31, warp = t >> 5;
    const int wm = warp >> 2, wn = warp & 3;

    const float4 lw = *(const float4*)&lnw[lane * 4];
    const float4 lb = *(const float4*)&lnb[lane * 4];

    // ---------- prologue: stage 5 W images + z for first block ----------
    #pragma unroll
    for (int m = 0; m < 5; ++m)
        stage_img(base, W_OFF(m), wimg(m), t);
    stage_z(base, z, blockIdx.x * 4, t);
    cp_commit();
    CP_WAIT(0);
    __syncthreads();                       // W + z0 ready

    layernorm_block(smem, warp, lane, lw, lb);   // zn for first block -> A
    if ((int)blockIdx.x + (int)gridDim.x < NBLOCKS) {
        stage_z(base, z, ((int)blockIdx.x + (int)gridDim.x) * 4, t);
        cp_commit();
    }
    __syncthreads();                       // A(zn_0) visible to all warps

    for (int blk = blockIdx.x; blk < NBLOCKS; blk += gridDim.x) {
        const int pbase = blk * 4;
        const bool has_next = (blk + (int)gridDim.x < NBLOCKS);

        // ---------- fused q|k -> S -> softmax -> P fragments (0.25 pre-folded) ----------
        uint32_t pf[2][4], plf[2][4];
        {
            float cq[4][4], ck[4][4];
            #pragma unroll
            for (int j = 0; j < 4; ++j)
                #pragma unroll
                for (int q = 0; q < 4; ++q) { cq[j][q] = 0.f; ck[j][q] = 0.f; }
            gemm_pair(base, W_OFF(0), W_OFF(1), wm, wn, lane, cq, ck);

            #pragma unroll
            for (int hh = 0; hh < 2; ++hh) {
                uint32_t qf[4], kf[4];
                qf[0] = h2bits(cq[2*hh][0],   cq[2*hh][1]);
                qf[1] = h2bits(cq[2*hh][2],   cq[2*hh][3]);
                qf[2] = h2bits(cq[2*hh+1][0], cq[2*hh+1][1]);
                qf[3] = h2bits(cq[2*hh+1][2], cq[2*hh+1][3]);
                kf[0] = h2bits(ck[2*hh][0],   ck[2*hh][1]);
                kf[1] = h2bits(ck[2*hh+1][0], ck[2*hh+1][1]);
                kf[2] = h2bits(ck[2*hh][2],   ck[2*hh][3]);
                kf[3] = h2bits(ck[2*hh+1][2], ck[2*hh+1][3]);

                float s0[4] = {0.f,0.f,0.f,0.f}, s1[4] = {0.f,0.f,0.f,0.f};
                mma_f16(s0, qf, &kf[0]);
                mma_f16(s1, qf, &kf[2]);

                float mlo = fmaxf(fmaxf(s0[0], s0[1]), fmaxf(s1[0], s1[1]));
                float mhi = fmaxf(fmaxf(s0[2], s0[3]), fmaxf(s1[2], s1[3]));
                mlo = fmaxf(mlo, __shfl_xor_sync(0xffffffffu, mlo, 1));
                mlo = fmaxf(mlo, __shfl_xor_sync(0xffffffffu, mlo, 2));
                mhi = fmaxf(mhi, __shfl_xor_sync(0xffffffffu, mhi, 1));
                mhi = fmaxf(mhi, __shfl_xor_sync(0xffffffffu, mhi, 2));
                s0[0] = __expf(s0[0] - mlo); s0[1] = __expf(s0[1] - mlo);
                s1[0] = __expf(s1[0] - mlo); s1[1] = __expf(s1[1] - mlo);
                s0[2] = __expf(s0[2] - mhi); s0[3] = __expf(s0[3] - mhi);
                s1[2] = __expf(s1[2] - mhi); s1[3] = __expf(s1[3] - mhi);
                float slo = s0[0] + s0[1] + s1[0] + s1[1];
                float shi = s0[2] + s0[3] + s1[2] + s1[3];
                slo += __shfl_xor_sync(0xffffffffu, slo, 1);
                slo += __shfl_xor_sync(0xffffffffu, slo, 2);
                shi += __shfl_xor_sync(0xffffffffu, shi, 1);
                shi += __shfl_xor_sync(0xffffffffu, shi, 2);
                const float ilo = 1.0f / slo, ihi = 1.0f / shi;
                s0[0] *= ilo; s0[1] *= ilo; s1[0] *= ilo; s1[1] *= ilo;
                s0[2] *= ihi; s0[3] *= ihi; s1[2] *= ihi; s1[3] *= ihi;

                pf[hh][0] = h2bits(s0[0], s0[1]);  plf[hh][0] = h2res(s0[0], s0[1], pf[hh][0]);
                pf[hh][1] = h2bits(s0[2], s0[3]);  plf[hh][1] = h2res(s0[2], s0[3], pf[hh][1]);
                pf[hh][2] = h2bits(s1[0], s1[1]);  plf[hh][2] = h2res(s1[0], s1[1], pf[hh][2]);
                pf[hh][3] = h2bits(s1[2], s1[3]);  plf[hh][3] = h2res(s1[2], s1[3], pf[hh][3]);
            }
        }

        // ---------- fused v|g -> O = P V (3-term) -> gate (oc in regs) ----------
        float oc[2][2][4];
        {
            float cv[4][4], cg[4][4];
            #pragma unroll
            for (int j = 0; j < 4; ++j)
                #pragma unroll
                for (int q = 0; q < 4; ++q) { cv[j][q] = 0.f; cg[j][q] = 0.f; }
            gemm_pair(base, W_OFF(2), W_OFF(3), wm, wn, lane, cv, cg);

            #pragma unroll
            for (int hh = 0; hh < 2; ++hh) {
                #pragma unroll
                for (int cb = 0; cb < 2; ++cb) {
                    const int nb = hh * 2 + cb;
                    const uint32_t m0 = h2bits(cv[nb][0], cv[nb][1]);
                    const uint32_t m1 = h2bits(cv[nb][2], cv[nb][3]);
                    const uint32_t r0 = h2res(cv[nb][0], cv[nb][1], m0);
                    const uint32_t r1 = h2res(cv[nb][2], cv[nb][3], m1);
                    uint32_t bh[2], bl[2];
                    bh[0] = movm(m0); bh[1] = movm(m1);
                    bl[0] = movm(r0); bl[1] = movm(r1);
                    float* o = oc[hh][cb];
                    o[0] = 0.f; o[1] = 0.f; o[2] = 0.f; o[3] = 0.f;
                    mma_f16(o, pf[hh],  bh);
                    mma_f16(o, plf[hh], bh);
                    mma_f16(o, pf[hh],  bl);
                }
            }

            // gate with sigmoid(cg + bg)
            #pragma unroll
            for (int hh = 0; hh < 2; ++hh) {
                #pragma unroll
                for (int cb = 0; cb < 2; ++cb) {
                    const int nb = hh * 2 + cb;
                    const int col = wn * 32 + nb * 8 + 2 * (lane & 3);
                    const float b0 = bg[col], b1 = bg[col + 1];
                    float* o = oc[hh][cb];
                    o[0] *= sigmoidf_(cg[nb][0] + b0);
                    o[1] *= sigmoidf_(cg[nb][1] + b1);
                    o[2] *= sigmoidf_(cg[nb][2] + b0);
                    o[3] *= sigmoidf_(cg[nb][3] + b1);
                }
            }
        }
        __syncthreads();             // all zn reads done (A free), before LN_next writes A

        // ---------- o-store || LN_next || z-prefetch (no internal barriers) ----------
        #pragma unroll
        for (int hh = 0; hh < 2; ++hh) {
            #pragma unroll
            for (int cb = 0; cb < 2; ++cb) {
                const int col = wn * 32 + (hh * 2 + cb) * 8 + 2 * (lane & 3);
                const int r = wm * 16 + (lane >> 2);
                store_o2(smem, r,     col, oc[hh][cb][0], oc[hh][cb][1]);
                store_o2(smem, r + 8, col, oc[hh][cb][2], oc[hh][cb][3]);
            }
        }
        if (has_next) {
            CP_WAIT(0);                                  // z_next landed
            layernorm_block(smem, warp, lane, lw, lb);   // zn_next -> A
            if (blk + 2 * (int)gridDim.x < NBLOCKS) {    // prefetch z_next_next
                stage_z(base, z, (blk + 2 * (int)gridDim.x) * 4, t);
                cp_commit();
            }
        }
        __syncthreads();             // o visible; A(zn_next) ready

        // ---------- out GEMM (single-pass): o @ Wo + bo ----------
        {
            float c[4][4];
            #pragma unroll
            for (int j = 0; j < 4; ++j) { c[j][0]=0.f; c[j][1]=0.f; c[j][2]=0.f; c[j][3]=0.f; }
            gemm_single(base, SM_O, W_OFF(4), wm, wn, lane, c);

            const int r  = wm * 16 + (lane >> 2);
            const int r8 = r + 8;
            const long long grow  = (long long)(r  & 15) * PAIRS + pbase + (r  >> 4);
            const long long grow8 = (long long)(r8 & 15) * PAIRS + pbase + (r8 >> 4);
            #pragma unroll
            for (int nb = 0; nb < 4; ++nb) {
                const int col = wn * 32 + nb * 8 + 2 * (lane & 3);
                const float b0 = bo[col], b1 = bo[col + 1];
                *(float2*)&out[grow  * 128 + col] = make_float2(c[nb][0] + b0, c[nb][1] + b1);
                *(float2*)&out[grow8 * 128 + col] = make_float2(c[nb][2] + b0, c[nb][3] + b1);
            }
        }
        // no barrier here: next qk reads A (written before 2nd sync), outGEMM read only SM_O
    }
}

// =====================================================================================
extern "C" void kernel_launch(void* const* d_in, const int* in_sizes, int n_in,
                              void* d_out, int out_size)
{
    (void)in_sizes; (void)n_in; (void)out_size;
    const float* z   = (const float*)d_in[0];
    const float* lnw = (const float*)d_in[1];
    const float* lnb = (const float*)d_in[2];
    const float* Wq  = (const float*)d_in[3];
    const float* Wk  = (const float*)d_in[4];
    const float* Wv  = (const float*)d_in[5];
    const float* Wg  = (const float*)d_in[6];
    const float* bg  = (const float*)d_in[7];
    const float* Wo  = (const float*)d_in[8];
    const float* bo  = (const float*)d_in[9];
    float* out = (float*)d_out;

    cudaFuncSetAttribute(kernel_fused, cudaFuncAttributeMaxDynamicSharedMemorySize, SMEM_TOTAL);

    kernel_prep<<<5, 256>>>(Wq, Wk, Wv, Wg, Wo);
    kernel_fused<<<GRID, NT, SMEM_TOTAL>>>(z, lnw, lnb, bg, bo, out);
}